// round 7
// baseline (speedup 1.0000x reference)
#include <cuda_runtime.h>
#include <cuda_bf16.h>
#include <stdint.h>

#define N_NODES 50000
#define N_EDGES 800000
#define N_GRAPHS 256
#define DIN0 32
#define HID 96
#define BN_EPS 1e-5f

// ---------------- device scratch (static, allowed) ----------------
__device__ float g_h[(size_t)N_NODES * HID];
__device__ float g_agg[(size_t)N_NODES * HID];
__device__ float g_z[(size_t)N_NODES * HID];
__device__ float g_pool[N_GRAPHS * HID];

// vectorized fire-and-forget global reduction (sm_90+)
__device__ __forceinline__ void red_add_v4(float* addr, float4 v) {
    asm volatile("red.global.add.v4.f32 [%0], {%1, %2, %3, %4};"
                 :: "l"(addr), "f"(v.x), "f"(v.y), "f"(v.z), "f"(v.w)
                 : "memory");
}

// ---------------- small kernels ----------------
__global__ void copy_x_kernel(const float* __restrict__ x) {
    int i = blockIdx.x * blockDim.x + threadIdx.x;
    int total = N_NODES * DIN0 / 4;
    if (i < total) ((float4*)g_agg)[i] = ((const float4*)x)[i];
}

// edge scatter: agg[dst] += h[src], one red.v4 per (edge, lane)
template<int DIN>
__global__ void edge_kernel(const float* __restrict__ h,
                            const int* __restrict__ ei,
                            float* __restrict__ agg) {
    const int VPR = DIN / 4;
    int t = blockIdx.x * blockDim.x + threadIdx.x;
    int e = t / VPR;
    int lane = t - e * VPR;
    if (e >= N_EDGES) return;
    int s = __ldg(&ei[e]);
    int d = __ldg(&ei[N_EDGES + e]);
    float4 v = *(const float4*)(h + (size_t)s * DIN + lane * 4);
    red_add_v4(agg + (size_t)d * DIN + lane * 4, v);
}

// ---------------- GEMM: out = epilogue(A[N x DIN] @ W[DIN x 96]) ----------------
// 192 threads = 16 row-threads x 12 col-threads; BM=128; microtile 8 rows x 8 cols.
// A k-tile TRANSPOSED in smem (As[kk][r]); KT=8, double-buffered.
// Per kk: 2 LDS.128 (a rows) + 2 LDS.128 (w cols) -> 64 FMA.
template<int DIN, bool HAS_BN, bool DUAL>
__global__ void __launch_bounds__(192, 3) gemm_kernel(
    const float* __restrict__ A, const float* __restrict__ W,
    const float* __restrict__ bias,
    const float* __restrict__ gamma, const float* __restrict__ beta,
    const float* __restrict__ rmean, const float* __restrict__ rvar,
    float* __restrict__ out, float* __restrict__ out2)
{
    constexpr int H = HID;
    constexpr int BM = 128;
    constexpr int KT = 8;
    constexpr int NKT = DIN / KT;
    constexpr int NV = BM * (KT / 4);        // 256 float4 per tile
    __shared__ float Ws[DIN * H];            // 12KB / 36KB
    __shared__ float As[2][KT][BM];          // 2 x 4KB

    const int tid = threadIdx.x;
    const int row0 = blockIdx.x * BM;

    for (int i = tid; i < DIN * H / 4; i += 192)
        ((float4*)Ws)[i] = ((const float4*)W)[i];

    const int row_t = tid & 15;          // 0..15
    const int col_t = tid >> 4;          // 0..11
    const int r0 = row_t * 8;            // 8 contiguous rows
    const int c0 = col_t * 8;            // 8 contiguous cols

    float acc[8][8];
    #pragma unroll
    for (int i = 0; i < 8; i++)
        #pragma unroll
        for (int j = 0; j < 8; j++) acc[i][j] = 0.f;

    float4 vst[2];

    // prologue: stage tile 0
    #pragma unroll
    for (int it = 0; it < 2; it++) {
        int i = tid + it * 192;
        if (i < NV) {
            int r = i & 127, kv = i >> 7;
            int gr = row0 + r;
            vst[it] = (gr < N_NODES)
                ? *(const float4*)(A + (size_t)gr * DIN + kv * 4)
                : make_float4(0.f, 0.f, 0.f, 0.f);
        }
    }
    #pragma unroll
    for (int it = 0; it < 2; it++) {
        int i = tid + it * 192;
        if (i < NV) {
            int r = i & 127, kv = i >> 7;
            As[0][kv * 4 + 0][r] = vst[it].x;
            As[0][kv * 4 + 1][r] = vst[it].y;
            As[0][kv * 4 + 2][r] = vst[it].z;
            As[0][kv * 4 + 3][r] = vst[it].w;
        }
    }
    __syncthreads();

    int buf = 0;
    for (int kt = 0; kt < NKT; kt++) {
        if (kt + 1 < NKT) {
            #pragma unroll
            for (int it = 0; it < 2; it++) {
                int i = tid + it * 192;
                if (i < NV) {
                    int r = i & 127, kv = i >> 7;
                    int gr = row0 + r;
                    vst[it] = (gr < N_NODES)
                        ? *(const float4*)(A + (size_t)gr * DIN + (kt + 1) * KT + kv * 4)
                        : make_float4(0.f, 0.f, 0.f, 0.f);
                }
            }
        }

        #pragma unroll
        for (int kk = 0; kk < KT; kk++) {
            const float4* ar = (const float4*)&As[buf][kk][r0];
            float4 a0 = ar[0], a1 = ar[1];
            const float4* wr = (const float4*)&Ws[(kt * KT + kk) * H + c0];
            float4 w0 = wr[0], w1 = wr[1];
            float a[8] = {a0.x, a0.y, a0.z, a0.w, a1.x, a1.y, a1.z, a1.w};
            float w[8] = {w0.x, w0.y, w0.z, w0.w, w1.x, w1.y, w1.z, w1.w};
            #pragma unroll
            for (int i = 0; i < 8; i++)
                #pragma unroll
                for (int j = 0; j < 8; j++)
                    acc[i][j] = fmaf(a[i], w[j], acc[i][j]);
        }

        if (kt + 1 < NKT) {
            #pragma unroll
            for (int it = 0; it < 2; it++) {
                int i = tid + it * 192;
                if (i < NV) {
                    int r = i & 127, kv = i >> 7;
                    As[buf ^ 1][kv * 4 + 0][r] = vst[it].x;
                    As[buf ^ 1][kv * 4 + 1][r] = vst[it].y;
                    As[buf ^ 1][kv * 4 + 2][r] = vst[it].z;
                    As[buf ^ 1][kv * 4 + 3][r] = vst[it].w;
                }
            }
            __syncthreads();
        }
        buf ^= 1;
    }

    // epilogue: (+bias), optional BN, relu, vectorized stores
    float sc[8], sh[8];
    #pragma unroll
    for (int j = 0; j < 8; j++) {
        int c = c0 + j;
        if (HAS_BN) {
            float s = gamma[c] * rsqrtf(rvar[c] + BN_EPS);
            sc[j] = s;
            sh[j] = (bias[c] - rmean[c]) * s + beta[c];
        } else {
            sc[j] = 1.f;
            sh[j] = bias[c];
        }
    }
    #pragma unroll
    for (int i = 0; i < 8; i++) {
        int gr = row0 + r0 + i;
        if (gr < N_NODES) {
            float v[8];
            #pragma unroll
            for (int j = 0; j < 8; j++)
                v[j] = fmaxf(fmaf(acc[i][j], sc[j], sh[j]), 0.f);
            float4 o0 = make_float4(v[0], v[1], v[2], v[3]);
            float4 o1 = make_float4(v[4], v[5], v[6], v[7]);
            *(float4*)(out + (size_t)gr * H + c0)     = o0;
            *(float4*)(out + (size_t)gr * H + c0 + 4) = o1;
            if (DUAL) {
                *(float4*)(out2 + (size_t)gr * H + c0)     = o0;
                *(float4*)(out2 + (size_t)gr * H + c0 + 4) = o1;
            }
        }
    }
}

// ---------------- pooling (batch sorted -> segment sums, no atomics) ----------
__global__ void __launch_bounds__(96) pool_kernel(const int* __restrict__ batch,
                                                  float* __restrict__ pool) {
    int b = blockIdx.x;
    int c = threadIdx.x;
    int lo = 0, hi = N_NODES;
    while (lo < hi) { int m = (lo + hi) >> 1; if (batch[m] < b) lo = m + 1; else hi = m; }
    int start = lo;
    hi = N_NODES;
    while (lo < hi) { int m = (lo + hi) >> 1; if (batch[m] < b + 1) lo = m + 1; else hi = m; }
    int end = lo;

    float acc = 0.f;
    for (int n = start; n < end; n++)
        acc += g_h[(size_t)n * HID + c];
    pool[b * HID + c] = acc;
}

__global__ void head_kernel(const int* __restrict__ r_target,
                            const float* __restrict__ head_w,
                            const float* __restrict__ head_b,
                            const float* __restrict__ pool,
                            float* __restrict__ out) {
    int b = threadIdx.x;
    if (b >= N_GRAPHS) return;
    int t = r_target[b];
    const float4* w = (const float4*)(head_w + (size_t)t * HID);
    const float4* p = (const float4*)(pool + (size_t)b * HID);
    float acc = 0.f;
    #pragma unroll
    for (int k = 0; k < HID / 4; k++) {
        float4 wv = w[k], pv = p[k];
        acc = fmaf(pv.x, wv.x, acc);
        acc = fmaf(pv.y, wv.y, acc);
        acc = fmaf(pv.z, wv.z, acc);
        acc = fmaf(pv.w, wv.w, acc);
    }
    out[b] = acc + head_b[t];
}

// ---------------- launch ----------------
extern "C" void kernel_launch(void* const* d_in, const int* in_sizes, int n_in,
                              void* d_out, int out_size) {
    const float* x    = (const float*)d_in[0];
    const int*   ei   = (const int*)d_in[1];
    const int*   bat  = (const int*)d_in[2];
    const int*   rtg  = (const int*)d_in[3];

    const float* w_in[3]  = {(const float*)d_in[4],  (const float*)d_in[12], (const float*)d_in[20]};
    const float* b_in[3]  = {(const float*)d_in[5],  (const float*)d_in[13], (const float*)d_in[21]};
    const float* gam[3]   = {(const float*)d_in[6],  (const float*)d_in[14], (const float*)d_in[22]};
    const float* bet[3]   = {(const float*)d_in[7],  (const float*)d_in[15], (const float*)d_in[23]};
    const float* rme[3]   = {(const float*)d_in[8],  (const float*)d_in[16], (const float*)d_in[24]};
    const float* rva[3]   = {(const float*)d_in[9],  (const float*)d_in[17], (const float*)d_in[25]};
    const float* w_out[3] = {(const float*)d_in[10], (const float*)d_in[18], (const float*)d_in[26]};
    const float* b_out[3] = {(const float*)d_in[11], (const float*)d_in[19], (const float*)d_in[27]};
    const float* head_w   = (const float*)d_in[28];
    const float* head_b   = (const float*)d_in[29];
    float* out = (float*)d_out;

    float *hbuf, *aggbuf, *zbuf, *poolbuf;
    cudaGetSymbolAddress((void**)&hbuf, g_h);
    cudaGetSymbolAddress((void**)&aggbuf, g_agg);
    cudaGetSymbolAddress((void**)&zbuf, g_z);
    cudaGetSymbolAddress((void**)&poolbuf, g_pool);

    const int TB = 256;
    const int GB = 192;
    const int gemm_blocks = (N_NODES + 127) / 128;

    // ---- layer 1 (Din=32) ----
    copy_x_kernel<<<(N_NODES * DIN0 / 4 + TB - 1) / TB, TB>>>(x);
    {
        int tot = N_EDGES * (DIN0 / 4);
        edge_kernel<DIN0><<<(tot + TB - 1) / TB, TB>>>(x, ei, aggbuf);
    }
    gemm_kernel<DIN0, true, false><<<gemm_blocks, GB>>>(
        aggbuf, w_in[0], b_in[0], gam[0], bet[0], rme[0], rva[0], zbuf, nullptr);
    gemm_kernel<HID, false, true><<<gemm_blocks, GB>>>(
        zbuf, w_out[0], b_out[0], nullptr, nullptr, nullptr, nullptr, hbuf, aggbuf);

    // ---- layer 2 ----
    {
        int tot = N_EDGES * (HID / 4);
        edge_kernel<HID><<<(tot + TB - 1) / TB, TB>>>(hbuf, ei, aggbuf);
    }
    gemm_kernel<HID, true, false><<<gemm_blocks, GB>>>(
        aggbuf, w_in[1], b_in[1], gam[1], bet[1], rme[1], rva[1], zbuf, nullptr);
    gemm_kernel<HID, false, true><<<gemm_blocks, GB>>>(
        zbuf, w_out[1], b_out[1], nullptr, nullptr, nullptr, nullptr, hbuf, aggbuf);

    // ---- layer 3 ----
    {
        int tot = N_EDGES * (HID / 4);
        edge_kernel<HID><<<(tot + TB - 1) / TB, TB>>>(hbuf, ei, aggbuf);
    }
    gemm_kernel<HID, true, false><<<gemm_blocks, GB>>>(
        aggbuf, w_in[2], b_in[2], gam[2], bet[2], rme[2], rva[2], zbuf, nullptr);
    gemm_kernel<HID, false, false><<<gemm_blocks, GB>>>(
        zbuf, w_out[2], b_out[2], nullptr, nullptr, nullptr, nullptr, hbuf, nullptr);

    // ---- pooling + head ----
    pool_kernel<<<N_GRAPHS, 96>>>(bat, poolbuf);
    head_kernel<<<1, 256>>>(rtg, head_w, head_b, poolbuf, out);
}

// round 8
// speedup vs baseline: 1.4024x; 1.4024x over previous
#include <cuda_runtime.h>
#include <cuda_bf16.h>
#include <stdint.h>

#define N_NODES 50000
#define N_EDGES 800000
#define N_GRAPHS 256
#define DIN0 32
#define HID 96
#define BN_EPS 1e-5f

// ---------------- device scratch (static, allowed) ----------------
__device__ float g_h[(size_t)N_NODES * HID];
__device__ float g_agg[(size_t)N_NODES * HID];
__device__ float g_z[(size_t)N_NODES * HID];
__device__ float g_pool[N_GRAPHS * HID];

// vectorized fire-and-forget global reduction (sm_90+)
__device__ __forceinline__ void red_add_v4(float* addr, float4 v) {
    asm volatile("red.global.add.v4.f32 [%0], {%1, %2, %3, %4};"
                 :: "l"(addr), "f"(v.x), "f"(v.y), "f"(v.z), "f"(v.w)
                 : "memory");
}

__device__ __forceinline__ float to_tf32(float x) {
    uint32_t u;
    asm("cvt.rna.tf32.f32 %0, %1;" : "=r"(u) : "f"(x));
    return __uint_as_float(u);
}

__device__ __forceinline__ void mma_tf32(float* c, uint32_t a0, uint32_t a1,
                                         uint32_t a2, uint32_t a3,
                                         uint32_t b0, uint32_t b1) {
    asm volatile(
        "mma.sync.aligned.m16n8k8.row.col.f32.tf32.tf32.f32 "
        "{%0,%1,%2,%3}, {%4,%5,%6,%7}, {%8,%9}, {%0,%1,%2,%3};"
        : "+f"(c[0]), "+f"(c[1]), "+f"(c[2]), "+f"(c[3])
        : "r"(a0), "r"(a1), "r"(a2), "r"(a3), "r"(b0), "r"(b1));
}

// ---------------- small kernels ----------------
__global__ void copy_x_kernel(const float* __restrict__ x) {
    int i = blockIdx.x * blockDim.x + threadIdx.x;
    int total = N_NODES * DIN0 / 4;
    if (i < total) ((float4*)g_agg)[i] = ((const float4*)x)[i];
}

// edge scatter: agg[dst] += h[src], one red.v4 per (edge, lane)
template<int DIN>
__global__ void edge_kernel(const float* __restrict__ h,
                            const int* __restrict__ ei,
                            float* __restrict__ agg) {
    const int VPR = DIN / 4;
    int t = blockIdx.x * blockDim.x + threadIdx.x;
    int e = t / VPR;
    int lane = t - e * VPR;
    if (e >= N_EDGES) return;
    int s = __ldg(&ei[e]);
    int d = __ldg(&ei[N_EDGES + e]);
    float4 v = *(const float4*)(h + (size_t)s * DIN + lane * 4);
    red_add_v4(agg + (size_t)d * DIN + lane * 4, v);
}

// ---------------- TF32 tensor-core GEMM: out = epi(A[N x DIN] @ W[DIN x 96]) --
// 256 threads = 8 warps. Block tile M=128 x N=96.
// Warp (mw=warp&3, nw=warp>>2): M-slab 32 rows (2 m16 frags), N-slab 48 (6 n8 frags).
// A k-chunks of 8, transposed in smem As[k][row] (stride 136), double-buffered.
// W transposed in smem Wt[n][k] (stride DIN+4) -> conflict-free B frags.
template<int DIN, bool HAS_BN, bool DUAL>
__global__ void __launch_bounds__(256, 2) gemm_kernel(
    const float* __restrict__ A, const float* __restrict__ W,
    const float* __restrict__ bias,
    const float* __restrict__ gamma, const float* __restrict__ beta,
    const float* __restrict__ rmean, const float* __restrict__ rvar,
    float* __restrict__ out, float* __restrict__ out2)
{
    constexpr int H = 96;
    constexpr int NKC = DIN / 8;
    constexpr int WSTR = DIN + 4;
    __shared__ float Wt[H * WSTR];          // W^T: Wt[n][k]
    __shared__ float As[2][8][136];         // A^T chunk: As[k][row]

    const int tid  = threadIdx.x;
    const int warp = tid >> 5;
    const int lane = tid & 31;
    const int g    = lane >> 2;             // 0..7
    const int tg   = lane & 3;              // 0..3
    const int mw   = warp & 3;              // 0..3 -> 32-row slab
    const int nw   = warp >> 2;             // 0..1 -> 48-col slab
    const int row0 = blockIdx.x * 128;

    // load W transposed + tf32-rounded
    for (int i = tid; i < DIN * H; i += 256) {
        int k = i / H, n = i - k * H;
        Wt[n * WSTR + k] = to_tf32(W[i]);
    }

    const int r  = tid & 127;
    const int kv = tid >> 7;                // 0..1 -> k sub-offset 4*kv

    float acc[2][6][4];
    #pragma unroll
    for (int mi = 0; mi < 2; mi++)
        #pragma unroll
        for (int ni = 0; ni < 6; ni++)
            #pragma unroll
            for (int q = 0; q < 4; q++) acc[mi][ni][q] = 0.f;

    // stage chunk 0
    {
        int gr = row0 + r;
        float4 v = (gr < N_NODES)
            ? *(const float4*)(A + (size_t)gr * DIN + kv * 4)
            : make_float4(0.f, 0.f, 0.f, 0.f);
        As[0][kv * 4 + 0][r] = to_tf32(v.x);
        As[0][kv * 4 + 1][r] = to_tf32(v.y);
        As[0][kv * 4 + 2][r] = to_tf32(v.z);
        As[0][kv * 4 + 3][r] = to_tf32(v.w);
    }
    __syncthreads();

    int buf = 0;
    for (int kt = 0; kt < NKC; kt++) {
        float4 nv;
        if (kt + 1 < NKC) {
            int gr = row0 + r;
            nv = (gr < N_NODES)
                ? *(const float4*)(A + (size_t)gr * DIN + (kt + 1) * 8 + kv * 4)
                : make_float4(0.f, 0.f, 0.f, 0.f);
        }

        const int kb = kt * 8;
        uint32_t bf[6][2];
        #pragma unroll
        for (int ni = 0; ni < 6; ni++) {
            int n = nw * 48 + ni * 8 + g;
            bf[ni][0] = __float_as_uint(Wt[n * WSTR + kb + tg]);
            bf[ni][1] = __float_as_uint(Wt[n * WSTR + kb + tg + 4]);
        }
        #pragma unroll
        for (int mi = 0; mi < 2; mi++) {
            int ra = mw * 32 + mi * 16 + g;
            uint32_t a0 = __float_as_uint(As[buf][tg][ra]);
            uint32_t a1 = __float_as_uint(As[buf][tg][ra + 8]);
            uint32_t a2 = __float_as_uint(As[buf][tg + 4][ra]);
            uint32_t a3 = __float_as_uint(As[buf][tg + 4][ra + 8]);
            #pragma unroll
            for (int ni = 0; ni < 6; ni++)
                mma_tf32(acc[mi][ni], a0, a1, a2, a3, bf[ni][0], bf[ni][1]);
        }

        if (kt + 1 < NKC) {
            As[buf ^ 1][kv * 4 + 0][r] = to_tf32(nv.x);
            As[buf ^ 1][kv * 4 + 1][r] = to_tf32(nv.y);
            As[buf ^ 1][kv * 4 + 2][r] = to_tf32(nv.z);
            As[buf ^ 1][kv * 4 + 3][r] = to_tf32(nv.w);
            __syncthreads();
        }
        buf ^= 1;
    }

    // epilogue: per-thread cols = nw*48 + ni*8 + 2*tg (+1)
    float sc[6][2], sh[6][2];
    #pragma unroll
    for (int ni = 0; ni < 6; ni++)
        #pragma unroll
        for (int jj = 0; jj < 2; jj++) {
            int c = nw * 48 + ni * 8 + 2 * tg + jj;
            if (HAS_BN) {
                float s = gamma[c] * rsqrtf(rvar[c] + BN_EPS);
                sc[ni][jj] = s;
                sh[ni][jj] = (bias[c] - rmean[c]) * s + beta[c];
            } else {
                sc[ni][jj] = 1.f;
                sh[ni][jj] = bias[c];
            }
        }

    #pragma unroll
    for (int mi = 0; mi < 2; mi++) {
        int ra = row0 + mw * 32 + mi * 16 + g;
        int rb = ra + 8;
        #pragma unroll
        for (int ni = 0; ni < 6; ni++) {
            int col = nw * 48 + ni * 8 + 2 * tg;
            if (ra < N_NODES) {
                float2 o;
                o.x = fmaxf(fmaf(acc[mi][ni][0], sc[ni][0], sh[ni][0]), 0.f);
                o.y = fmaxf(fmaf(acc[mi][ni][1], sc[ni][1], sh[ni][1]), 0.f);
                *(float2*)(out + (size_t)ra * H + col) = o;
                if (DUAL) *(float2*)(out2 + (size_t)ra * H + col) = o;
            }
            if (rb < N_NODES) {
                float2 o;
                o.x = fmaxf(fmaf(acc[mi][ni][2], sc[ni][0], sh[ni][0]), 0.f);
                o.y = fmaxf(fmaf(acc[mi][ni][3], sc[ni][1], sh[ni][1]), 0.f);
                *(float2*)(out + (size_t)rb * H + col) = o;
                if (DUAL) *(float2*)(out2 + (size_t)rb * H + col) = o;
            }
        }
    }
}

// ---------------- pooling (batch sorted -> segment sums, no atomics) ----------
__global__ void __launch_bounds__(96) pool_kernel(const int* __restrict__ batch,
                                                  float* __restrict__ pool) {
    int b = blockIdx.x;
    int c = threadIdx.x;
    int lo = 0, hi = N_NODES;
    while (lo < hi) { int m = (lo + hi) >> 1; if (batch[m] < b) lo = m + 1; else hi = m; }
    int start = lo;
    hi = N_NODES;
    while (lo < hi) { int m = (lo + hi) >> 1; if (batch[m] < b + 1) lo = m + 1; else hi = m; }
    int end = lo;

    float acc = 0.f;
    for (int n = start; n < end; n++)
        acc += g_h[(size_t)n * HID + c];
    pool[b * HID + c] = acc;
}

__global__ void head_kernel(const int* __restrict__ r_target,
                            const float* __restrict__ head_w,
                            const float* __restrict__ head_b,
                            const float* __restrict__ pool,
                            float* __restrict__ out) {
    int b = threadIdx.x;
    if (b >= N_GRAPHS) return;
    int t = r_target[b];
    const float4* w = (const float4*)(head_w + (size_t)t * HID);
    const float4* p = (const float4*)(pool + (size_t)b * HID);
    float acc = 0.f;
    #pragma unroll
    for (int k = 0; k < HID / 4; k++) {
        float4 wv = w[k], pv = p[k];
        acc = fmaf(pv.x, wv.x, acc);
        acc = fmaf(pv.y, wv.y, acc);
        acc = fmaf(pv.z, wv.z, acc);
        acc = fmaf(pv.w, wv.w, acc);
    }
    out[b] = acc + head_b[t];
}

// ---------------- launch ----------------
extern "C" void kernel_launch(void* const* d_in, const int* in_sizes, int n_in,
                              void* d_out, int out_size) {
    const float* x    = (const float*)d_in[0];
    const int*   ei   = (const int*)d_in[1];
    const int*   bat  = (const int*)d_in[2];
    const int*   rtg  = (const int*)d_in[3];

    const float* w_in[3]  = {(const float*)d_in[4],  (const float*)d_in[12], (const float*)d_in[20]};
    const float* b_in[3]  = {(const float*)d_in[5],  (const float*)d_in[13], (const float*)d_in[21]};
    const float* gam[3]   = {(const float*)d_in[6],  (const float*)d_in[14], (const float*)d_in[22]};
    const float* bet[3]   = {(const float*)d_in[7],  (const float*)d_in[15], (const float*)d_in[23]};
    const float* rme[3]   = {(const float*)d_in[8],  (const float*)d_in[16], (const float*)d_in[24]};
    const float* rva[3]   = {(const float*)d_in[9],  (const float*)d_in[17], (const float*)d_in[25]};
    const float* w_out[3] = {(const float*)d_in[10], (const float*)d_in[18], (const float*)d_in[26]};
    const float* b_out[3] = {(const float*)d_in[11], (const float*)d_in[19], (const float*)d_in[27]};
    const float* head_w   = (const float*)d_in[28];
    const float* head_b   = (const float*)d_in[29];
    float* out = (float*)d_out;

    float *hbuf, *aggbuf, *zbuf, *poolbuf;
    cudaGetSymbolAddress((void**)&hbuf, g_h);
    cudaGetSymbolAddress((void**)&aggbuf, g_agg);
    cudaGetSymbolAddress((void**)&zbuf, g_z);
    cudaGetSymbolAddress((void**)&poolbuf, g_pool);

    const int TB = 256;
    const int gemm_blocks = (N_NODES + 127) / 128;

    // ---- layer 1 (Din=32) ----
    copy_x_kernel<<<(N_NODES * DIN0 / 4 + TB - 1) / TB, TB>>>(x);
    {
        int tot = N_EDGES * (DIN0 / 4);
        edge_kernel<DIN0><<<(tot + TB - 1) / TB, TB>>>(x, ei, aggbuf);
    }
    gemm_kernel<DIN0, true, false><<<gemm_blocks, TB>>>(
        aggbuf, w_in[0], b_in[0], gam[0], bet[0], rme[0], rva[0], zbuf, nullptr);
    gemm_kernel<HID, false, true><<<gemm_blocks, TB>>>(
        zbuf, w_out[0], b_out[0], nullptr, nullptr, nullptr, nullptr, hbuf, aggbuf);

    // ---- layer 2 ----
    {
        int tot = N_EDGES * (HID / 4);
        edge_kernel<HID><<<(tot + TB - 1) / TB, TB>>>(hbuf, ei, aggbuf);
    }
    gemm_kernel<HID, true, false><<<gemm_blocks, TB>>>(
        aggbuf, w_in[1], b_in[1], gam[1], bet[1], rme[1], rva[1], zbuf, nullptr);
    gemm_kernel<HID, false, true><<<gemm_blocks, TB>>>(
        zbuf, w_out[1], b_out[1], nullptr, nullptr, nullptr, nullptr, hbuf, aggbuf);

    // ---- layer 3 ----
    {
        int tot = N_EDGES * (HID / 4);
        edge_kernel<HID><<<(tot + TB - 1) / TB, TB>>>(hbuf, ei, aggbuf);
    }
    gemm_kernel<HID, true, false><<<gemm_blocks, TB>>>(
        aggbuf, w_in[2], b_in[2], gam[2], bet[2], rme[2], rva[2], zbuf, nullptr);
    gemm_kernel<HID, false, false><<<gemm_blocks, TB>>>(
        zbuf, w_out[2], b_out[2], nullptr, nullptr, nullptr, nullptr, hbuf, nullptr);

    // ---- pooling + head ----
    pool_kernel<<<N_GRAPHS, 96>>>(bat, poolbuf);
    head_kernel<<<1, 256>>>(rtg, head_w, head_b, poolbuf, out);
}